// round 1
// baseline (speedup 1.0000x reference)
#include <cuda_runtime.h>

// Problem constants
#define B_  2
#define S_  2048
#define D_  1024
#define H_  16
#define DH_ 64
#define MTOT (B_*S_)   // 4096

// Scratch (device globals: allocation-free)
__device__ float g_qT[B_*H_*DH_*S_];   // [b,h,d,s]  (scaled by 1/8)
__device__ float g_kT[B_*H_*DH_*S_];   // [b,h,d,s]
__device__ float g_v [B_*H_*S_*DH_];   // [b,h,s,e]
__device__ float g_ctx[MTOT*D_];       // [b*s, h*e]

// ---------------------------------------------------------------------------
// GEMM tiling
#define BM 128
#define BN 128
#define BK 8

// QKV projection: C = x[4096,1024] @ W[h][1024,64] (+bias), z selects Q/K/V.
// Q,K written transposed [b,h,d,s]; V written [b,h,s,e]. Q scaled by 0.125.
__global__ __launch_bounds__(256)
void qkv_kernel(const float* __restrict__ x,
                const float* __restrict__ Wq, const float* __restrict__ Wk,
                const float* __restrict__ Wv,
                const float* __restrict__ bq, const float* __restrict__ bk,
                const float* __restrict__ bv)
{
    const int z = blockIdx.z;
    const float* Wm   = (z == 0) ? Wq : (z == 1) ? Wk : Wv;
    const float* bias = (z == 0) ? bq : (z == 1) ? bk : bv;

    __shared__ float As[BK][BM+4];
    __shared__ float Bs[BK][BN+4];

    const int tid = threadIdx.x;
    const int tx = tid & 15, ty = tid >> 4;
    const int tm = ty * 8, tn = tx * 8;
    const int m0 = blockIdx.y * BM, n0 = blockIdx.x * BN;

    float acc[8][8];
#pragma unroll
    for (int i = 0; i < 8; i++)
#pragma unroll
        for (int j = 0; j < 8; j++) acc[i][j] = 0.f;

    const int arow = tid >> 1, acol = (tid & 1) * 4;
    const int brow = tid >> 5, bcol = (tid & 31) * 4;
    const float* xA = x + (size_t)(m0 + arow) * D_ + acol;
    const int nB = n0 + bcol;
    const int hB = nB >> 6, eB = nB & 63;
    const float* WB = Wm + (size_t)hB * (D_ * DH_) + brow * DH_ + eB;

    for (int k0 = 0; k0 < D_; k0 += BK) {
        float4 a4 = *(const float4*)(xA + k0);
        float4 b4 = *(const float4*)(WB + (size_t)k0 * DH_);
        As[acol+0][arow] = a4.x;
        As[acol+1][arow] = a4.y;
        As[acol+2][arow] = a4.z;
        As[acol+3][arow] = a4.w;
        *(float4*)&Bs[brow][bcol] = b4;
        __syncthreads();
#pragma unroll
        for (int kk = 0; kk < BK; kk++) {
            float4 a0 = *(float4*)&As[kk][tm];
            float4 a1 = *(float4*)&As[kk][tm+4];
            float4 b0 = *(float4*)&Bs[kk][tn];
            float4 b1 = *(float4*)&Bs[kk][tn+4];
            float a[8] = {a0.x,a0.y,a0.z,a0.w,a1.x,a1.y,a1.z,a1.w};
            float b[8] = {b0.x,b0.y,b0.z,b0.w,b1.x,b1.y,b1.z,b1.w};
#pragma unroll
            for (int i = 0; i < 8; i++)
#pragma unroll
                for (int j = 0; j < 8; j++) acc[i][j] = fmaf(a[i], b[j], acc[i][j]);
        }
        __syncthreads();
    }

    float bb[8];
#pragma unroll
    for (int j = 0; j < 8; j++) bb[j] = bias[n0 + tn + j];

    const int bidx  = m0 >> 11;           // batch (BM=128 never crosses S)
    const int sbase = (m0 & (S_-1)) + tm;

    if (z == 2) {
        // V: [b,h,s,e]; block of 8 n never crosses a head boundary
        const int n = n0 + tn;
        const int h = n >> 6, e0 = n & 63;
#pragma unroll
        for (int i = 0; i < 8; i++) {
            const int s = sbase + i;
            float* p = g_v + ((size_t)(bidx * H_ + h) * S_ + s) * DH_ + e0;
            float4 v0 = {acc[i][0]+bb[0], acc[i][1]+bb[1], acc[i][2]+bb[2], acc[i][3]+bb[3]};
            float4 v1 = {acc[i][4]+bb[4], acc[i][5]+bb[5], acc[i][6]+bb[6], acc[i][7]+bb[7]};
            *(float4*)p       = v0;
            *(float4*)(p + 4) = v1;
        }
    } else {
        float* dst = (z == 0) ? g_qT : g_kT;
        const float scale = (z == 0) ? 0.125f : 1.0f;   // fold 1/sqrt(DH) into Q
#pragma unroll
        for (int j = 0; j < 8; j++) {
            const int n = n0 + tn + j;
            const int h = n >> 6, e = n & 63;
            float* p = dst + ((size_t)(bidx * H_ + h) * DH_ + e) * S_ + sbase;
            float4 v0 = {(acc[0][j]+bb[j])*scale, (acc[1][j]+bb[j])*scale,
                         (acc[2][j]+bb[j])*scale, (acc[3][j]+bb[j])*scale};
            float4 v1 = {(acc[4][j]+bb[j])*scale, (acc[5][j]+bb[j])*scale,
                         (acc[6][j]+bb[j])*scale, (acc[7][j]+bb[j])*scale};
            *(float4*)p       = v0;
            *(float4*)(p + 4) = v1;
        }
    }
}

// ---------------------------------------------------------------------------
// Flash attention: grid (S/64, B*H), 256 threads. Warp w owns q-rows w*8..w*8+7.
__global__ __launch_bounds__(256)
void attn_kernel()
{
    __shared__ float QsT[64][64];   // [d][row]
    __shared__ float KP [64][64];   // KsT [d][key], then P [row][key]
    __shared__ float Vs [64][64];   // [key][e]

    const int tid  = threadIdx.x;
    const int lane = tid & 31;
    const int w    = tid >> 5;
    const int qb   = blockIdx.x;
    const int bh   = blockIdx.y;

    const float* qbase = g_qT + (size_t)bh * (DH_ * S_);
    const float* kbase = g_kT + (size_t)bh * (DH_ * S_);
    const float* vbase = g_v  + (size_t)bh * (S_ * DH_);

#pragma unroll
    for (int c = 0; c < 4; c++) {
        int lin = c * 1024 + tid * 4;
        int d = lin >> 6, r = lin & 63;
        *(float4*)&QsT[d][r] = *(const float4*)(qbase + (size_t)d * S_ + qb * 64 + r);
    }

    float acc0[8], acc1[8], mrow[8], lrow[8];
#pragma unroll
    for (int r = 0; r < 8; r++) { acc0[r]=0.f; acc1[r]=0.f; mrow[r]=-1e30f; lrow[r]=0.f; }

    const int k0i = lane, k1i = lane + 32;

    for (int kb = 0; kb < S_/64; kb++) {
        __syncthreads();   // prev PV done before overwriting KP/Vs (also covers QsT 1st iter)
#pragma unroll
        for (int c = 0; c < 4; c++) {
            int lin = c * 1024 + tid * 4;
            int d = lin >> 6, r = lin & 63;
            *(float4*)&KP[d][r] = *(const float4*)(kbase + (size_t)d * S_ + kb * 64 + r);
        }
#pragma unroll
        for (int c = 0; c < 4; c++) {
            int lin = c * 1024 + tid * 4;
            int kk = lin >> 6, e = lin & 63;
            *(float4*)&Vs[kk][e] = *(const float4*)(vbase + (size_t)(kb * 64 + kk) * DH_ + e);
        }
        __syncthreads();

        // ---- scores: S = Q K^T (scale already folded into Q) ----
        float s0[8], s1[8];
#pragma unroll
        for (int r = 0; r < 8; r++) { s0[r]=0.f; s1[r]=0.f; }
#pragma unroll 16
        for (int d = 0; d < 64; d++) {
            float4 qa = *(float4*)&QsT[d][w*8];
            float4 qc = *(float4*)&QsT[d][w*8+4];
            float kv0 = KP[d][k0i];
            float kv1 = KP[d][k1i];
            s0[0]=fmaf(qa.x,kv0,s0[0]); s1[0]=fmaf(qa.x,kv1,s1[0]);
            s0[1]=fmaf(qa.y,kv0,s0[1]); s1[1]=fmaf(qa.y,kv1,s1[1]);
            s0[2]=fmaf(qa.z,kv0,s0[2]); s1[2]=fmaf(qa.z,kv1,s1[2]);
            s0[3]=fmaf(qa.w,kv0,s0[3]); s1[3]=fmaf(qa.w,kv1,s1[3]);
            s0[4]=fmaf(qc.x,kv0,s0[4]); s1[4]=fmaf(qc.x,kv1,s1[4]);
            s0[5]=fmaf(qc.y,kv0,s0[5]); s1[5]=fmaf(qc.y,kv1,s1[5]);
            s0[6]=fmaf(qc.z,kv0,s0[6]); s1[6]=fmaf(qc.z,kv1,s1[6]);
            s0[7]=fmaf(qc.w,kv0,s0[7]); s1[7]=fmaf(qc.w,kv1,s1[7]);
        }

        // ---- online softmax (per warp-owned row) ----
        float p0[8], p1[8];
#pragma unroll
        for (int r = 0; r < 8; r++) {
            float mx = fmaxf(s0[r], s1[r]);
#pragma unroll
            for (int off = 16; off > 0; off >>= 1)
                mx = fmaxf(mx, __shfl_xor_sync(0xffffffffu, mx, off));
            float mnew = fmaxf(mrow[r], mx);
            float corr = __expf(mrow[r] - mnew);
            mrow[r] = mnew;
            p0[r] = __expf(s0[r] - mnew);
            p1[r] = __expf(s1[r] - mnew);
            float ps = p0[r] + p1[r];
#pragma unroll
            for (int off = 16; off > 0; off >>= 1)
                ps += __shfl_xor_sync(0xffffffffu, ps, off);
            lrow[r] = lrow[r] * corr + ps;
            acc0[r] *= corr;
            acc1[r] *= corr;
        }

        __syncthreads();   // everyone done reading KP (as K) before P overwrites it
#pragma unroll
        for (int r = 0; r < 8; r++) {
            KP[w*8+r][k0i] = p0[r];
            KP[w*8+r][k1i] = p1[r];
        }
        __syncwarp();      // rows are warp-private; warp-level ordering suffices

        // ---- PV accumulate ----
        for (int k4 = 0; k4 < 16; k4++) {
            float4 pr[8];
#pragma unroll
            for (int r = 0; r < 8; r++) pr[r] = *(float4*)&KP[w*8+r][k4*4];
#pragma unroll
            for (int kk = 0; kk < 4; kk++) {
                float v0 = Vs[k4*4+kk][k0i];
                float v1 = Vs[k4*4+kk][k1i];
#pragma unroll
                for (int r = 0; r < 8; r++) {
                    float pv = (kk==0) ? pr[r].x : (kk==1) ? pr[r].y : (kk==2) ? pr[r].z : pr[r].w;
                    acc0[r] = fmaf(pv, v0, acc0[r]);
                    acc1[r] = fmaf(pv, v1, acc1[r]);
                }
            }
        }
    }

    // epilogue: ctx[b, s, h*64+d]
    const int bidx = bh >> 4, h = bh & 15;
    const int sq0 = qb * 64 + w * 8;
#pragma unroll
    for (int r = 0; r < 8; r++) {
        float inv = 1.0f / lrow[r];
        float* p = g_ctx + (size_t)(bidx * S_ + sq0 + r) * D_ + h * DH_;
        p[lane]      = acc0[r] * inv;
        p[lane + 32] = acc1[r] * inv;
    }
}

// ---------------------------------------------------------------------------
// Output projection: out = ctx[4096,1024] @ Wo[1024,1024] + bo
__global__ __launch_bounds__(256)
void proj_kernel(const float* __restrict__ Wo, const float* __restrict__ bo,
                 float* __restrict__ out)
{
    __shared__ float As[BK][BM+4];
    __shared__ float Bs[BK][BN+4];

    const int tid = threadIdx.x;
    const int tx = tid & 15, ty = tid >> 4;
    const int tm = ty * 8, tn = tx * 8;
    const int m0 = blockIdx.y * BM, n0 = blockIdx.x * BN;

    float acc[8][8];
#pragma unroll
    for (int i = 0; i < 8; i++)
#pragma unroll
        for (int j = 0; j < 8; j++) acc[i][j] = 0.f;

    const int arow = tid >> 1, acol = (tid & 1) * 4;
    const int brow = tid >> 5, bcol = (tid & 31) * 4;
    const float* xA = g_ctx + (size_t)(m0 + arow) * D_ + acol;
    const float* WB = Wo + (size_t)brow * D_ + n0 + bcol;

    for (int k0 = 0; k0 < D_; k0 += BK) {
        float4 a4 = *(const float4*)(xA + k0);
        float4 b4 = *(const float4*)(WB + (size_t)k0 * D_);
        As[acol+0][arow] = a4.x;
        As[acol+1][arow] = a4.y;
        As[acol+2][arow] = a4.z;
        As[acol+3][arow] = a4.w;
        *(float4*)&Bs[brow][bcol] = b4;
        __syncthreads();
#pragma unroll
        for (int kk = 0; kk < BK; kk++) {
            float4 a0 = *(float4*)&As[kk][tm];
            float4 a1 = *(float4*)&As[kk][tm+4];
            float4 b0 = *(float4*)&Bs[kk][tn];
            float4 b1 = *(float4*)&Bs[kk][tn+4];
            float a[8] = {a0.x,a0.y,a0.z,a0.w,a1.x,a1.y,a1.z,a1.w};
            float b[8] = {b0.x,b0.y,b0.z,b0.w,b1.x,b1.y,b1.z,b1.w};
#pragma unroll
            for (int i = 0; i < 8; i++)
#pragma unroll
                for (int j = 0; j < 8; j++) acc[i][j] = fmaf(a[i], b[j], acc[i][j]);
        }
        __syncthreads();
    }

    float bb[8];
#pragma unroll
    for (int j = 0; j < 8; j++) bb[j] = bo[n0 + tn + j];
#pragma unroll
    for (int i = 0; i < 8; i++) {
        float* p = out + (size_t)(m0 + tm + i) * D_ + n0 + tn;
        float4 v0 = {acc[i][0]+bb[0], acc[i][1]+bb[1], acc[i][2]+bb[2], acc[i][3]+bb[3]};
        float4 v1 = {acc[i][4]+bb[4], acc[i][5]+bb[5], acc[i][6]+bb[6], acc[i][7]+bb[7]};
        *(float4*)p       = v0;
        *(float4*)(p + 4) = v1;
    }
}

// ---------------------------------------------------------------------------
extern "C" void kernel_launch(void* const* d_in, const int* in_sizes, int n_in,
                              void* d_out, int out_size)
{
    const float* x  = (const float*)d_in[0];
    const float* Wq = (const float*)d_in[1];
    const float* bq = (const float*)d_in[2];
    const float* Wk = (const float*)d_in[3];
    const float* bk = (const float*)d_in[4];
    const float* Wv = (const float*)d_in[5];
    const float* bv = (const float*)d_in[6];
    const float* Wo = (const float*)d_in[7];
    const float* bo = (const float*)d_in[8];
    float* out = (float*)d_out;

    dim3 gQKV(D_/BN, MTOT/BM, 3);     // (8, 32, 3)
    qkv_kernel<<<gQKV, 256>>>(x, Wq, Wk, Wv, bq, bk, bv);

    dim3 gAttn(S_/64, B_*H_);         // (32, 32)
    attn_kernel<<<gAttn, 256>>>();

    dim3 gProj(D_/BN, MTOT/BM);       // (8, 32)
    proj_kernel<<<gProj, 256>>>(Wo, bo, out);
}

// round 3
// speedup vs baseline: 2.8146x; 2.8146x over previous
#include <cuda_runtime.h>
#include <cuda_bf16.h>
#include <cstdint>

// ---------------------------------------------------------------------------
// Problem constants
#define B_   2
#define S_   2048
#define D_   1024
#define H_   16
#define DH_  64
#define MTOT (B_*S_)     // 4096
#define NQKV (3*D_)      // 3072

// ---------------------------------------------------------------------------
// Device-global scratch (allocation-free)
__device__ __nv_bfloat16 g_xHi[MTOT*D_];    // x split, [m][k]
__device__ __nv_bfloat16 g_xLo[MTOT*D_];
__device__ __nv_bfloat16 g_wHi[NQKV*D_];    // qkv weights, [n][k], n = z*1024+h*64+e
__device__ __nv_bfloat16 g_wLo[NQKV*D_];
__device__ __nv_bfloat16 g_woHi[D_*D_];     // Wo^T, [n][k]
__device__ __nv_bfloat16 g_woLo[D_*D_];
__device__ __nv_bfloat16 g_cHi[MTOT*D_];    // ctx split, [m][k]
__device__ __nv_bfloat16 g_cLo[MTOT*D_];

__device__ __nv_bfloat16 g_qHi[B_*H_*S_*DH_];  // [b,h,s,e], Q scaled by 1/8
__device__ __nv_bfloat16 g_qLo[B_*H_*S_*DH_];
__device__ __nv_bfloat16 g_kHi[B_*H_*S_*DH_];
__device__ __nv_bfloat16 g_kLo[B_*H_*S_*DH_];
__device__ __nv_bfloat16 g_vHi[B_*H_*S_*DH_];
__device__ __nv_bfloat16 g_vLo[B_*H_*S_*DH_];

// ---------------------------------------------------------------------------
// Baseline-PTX helpers (no sm_103a-only features)
__device__ __forceinline__ uint32_t smem_u32(const void* p) {
    uint32_t a;
    asm("{ .reg .u64 t; cvta.to.shared.u64 t, %1; cvt.u32.u64 %0, t; }" : "=r"(a) : "l"(p));
    return a;
}
__device__ __forceinline__ void ldsm4(uint32_t* r, uint32_t addr) {
    asm volatile("ldmatrix.sync.aligned.m8n8.x4.shared.b16 {%0,%1,%2,%3}, [%4];"
        : "=r"(r[0]), "=r"(r[1]), "=r"(r[2]), "=r"(r[3]) : "r"(addr));
}
__device__ __forceinline__ void ldsm4t(uint32_t* r, uint32_t addr) {
    asm volatile("ldmatrix.sync.aligned.m8n8.x4.trans.shared.b16 {%0,%1,%2,%3}, [%4];"
        : "=r"(r[0]), "=r"(r[1]), "=r"(r[2]), "=r"(r[3]) : "r"(addr));
}
__device__ __forceinline__ void mma_bf16(float* c, const uint32_t* a, const uint32_t* b) {
    asm volatile("mma.sync.aligned.m16n8k16.row.col.f32.bf16.bf16.f32 "
        "{%0,%1,%2,%3}, {%4,%5,%6,%7}, {%8,%9}, {%0,%1,%2,%3};"
        : "+f"(c[0]), "+f"(c[1]), "+f"(c[2]), "+f"(c[3])
        : "r"(a[0]), "r"(a[1]), "r"(a[2]), "r"(a[3]), "r"(b[0]), "r"(b[1]));
}
__device__ __forceinline__ void cpasync16(uint32_t dst, const void* src) {
    asm volatile("cp.async.cg.shared.global [%0], [%1], 16;" :: "r"(dst), "l"(src) : "memory");
}
#define CP_COMMIT() asm volatile("cp.async.commit_group;" ::: "memory")
#define CP_WAIT(n)  asm volatile("cp.async.wait_group %0;" :: "n"(n) : "memory")

// fp32 -> (bf16 hi, bf16 lo)
__device__ __forceinline__ void split_bf16(float v, __nv_bfloat16& hi, __nv_bfloat16& lo) {
    hi = __float2bfloat16(v);
    lo = __float2bfloat16(v - __bfloat162float(hi));
}
// pack two fp32 into bf16x2 hi-word and lo-word fragments (x -> low 16 bits)
__device__ __forceinline__ void pack_hl(float x, float y, uint32_t& hi, uint32_t& lo) {
    __nv_bfloat16 hx, lx, hy, ly;
    split_bf16(x, hx, lx);
    split_bf16(y, hy, ly);
    __nv_bfloat162 h2; h2.x = hx; h2.y = hy;
    __nv_bfloat162 l2; l2.x = lx; l2.y = ly;
    hi = *(uint32_t*)&h2;
    lo = *(uint32_t*)&l2;
}

// ---------------------------------------------------------------------------
// Conversion kernels
__global__ __launch_bounds__(256) void cvt_x_kernel(const float* __restrict__ x) {
    int i = blockIdx.x * 256 + threadIdx.x;
    float4 v = ((const float4*)x)[i];
    __nv_bfloat16 h0,h1,h2,h3,l0,l1,l2,l3;
    split_bf16(v.x,h0,l0); split_bf16(v.y,h1,l1);
    split_bf16(v.z,h2,l2); split_bf16(v.w,h3,l3);
    __nv_bfloat162 hA{h0,h1}, hB{h2,h3}, lA{l0,l1}, lB{l2,l3};
    ((__nv_bfloat162*)g_xHi)[2*i]   = hA;
    ((__nv_bfloat162*)g_xHi)[2*i+1] = hB;
    ((__nv_bfloat162*)g_xLo)[2*i]   = lA;
    ((__nv_bfloat162*)g_xLo)[2*i+1] = lB;
}

// Transpose-convert: in [R][C] fp32 (slab per blockIdx.z) -> out[c][r] hi/lo bf16
__global__ __launch_bounds__(256)
void cvt_T_kernel(const float* __restrict__ in,
                  __nv_bfloat16* __restrict__ oh, __nv_bfloat16* __restrict__ ol,
                  int R, int C)
{
    __shared__ float tb[32][33];
    const size_t slab = (size_t)blockIdx.z * R * C;
    const float* src = in + slab;
    const int r0 = blockIdx.x * 32, c0 = blockIdx.y * 32;
    const int tx = threadIdx.x, ty = threadIdx.y;   // (32, 8)
#pragma unroll
    for (int i = 0; i < 4; i++)
        tb[ty + i*8][tx] = src[(size_t)(r0 + ty + i*8) * C + (c0 + tx)];
    __syncthreads();
#pragma unroll
    for (int i = 0; i < 4; i++) {
        float v = tb[tx][ty + i*8];
        __nv_bfloat16 hi, lo; split_bf16(v, hi, lo);
        size_t idx = slab + (size_t)(c0 + ty + i*8) * R + (r0 + tx);
        oh[idx] = hi; ol[idx] = lo;
    }
}

// ---------------------------------------------------------------------------
// mma.sync GEMM: C[128x128] per CTA, K=1024 in 16 chunks of 64.
// smem tile: 128 rows x (64+8) bf16 = 144B rows (conflict-free ldmatrix).
#define RB     144
#define GTILE  (128*RB)                 // 18432
#define GEMM_SMEM (2*4*GTILE)           // 147456

template <int MODE>
__global__ __launch_bounds__(256)
void mma_gemm(const float* __restrict__ bq, const float* __restrict__ bk,
              const float* __restrict__ bv, const float* __restrict__ bo,
              float* __restrict__ out)
{
    extern __shared__ char smem[];
    const uint32_t sb = smem_u32(smem);
    const int tid = threadIdx.x, w = tid >> 5, t = tid & 31;
    const int m0 = blockIdx.y * 128, n0 = blockIdx.x * 128;
    const int mw = (w & 3) * 32, nw = (w >> 2) * 64;

    const __nv_bfloat16* Ah = (MODE == 0) ? g_xHi : g_cHi;
    const __nv_bfloat16* Al = (MODE == 0) ? g_xLo : g_cLo;
    const __nv_bfloat16* Bh = (MODE == 0) ? g_wHi : g_woHi;
    const __nv_bfloat16* Bl = (MODE == 0) ? g_wLo : g_woLo;

    float c[2][8][4];
#pragma unroll
    for (int i = 0; i < 2; i++)
#pragma unroll
        for (int j = 0; j < 8; j++)
#pragma unroll
            for (int q = 0; q < 4; q++) c[i][j][q] = 0.f;

    const int u  = tid & 7;        // 16B unit in 128B payload row
    const int r0 = tid >> 3;       // 32 rows per pass

    // ---- prologue: load chunk 0 into stage 0
#pragma unroll
    for (int p = 0; p < 4; p++) {
        int row = r0 + p * 32;
        uint32_t d = sb + row * RB + u * 16;
        cpasync16(d,             Ah + (size_t)(m0 + row) * D_ + u * 8);
        cpasync16(d + GTILE,     Al + (size_t)(m0 + row) * D_ + u * 8);
        cpasync16(d + 2*GTILE,   Bh + (size_t)(n0 + row) * D_ + u * 8);
        cpasync16(d + 3*GTILE,   Bl + (size_t)(n0 + row) * D_ + u * 8);
    }
    CP_COMMIT();

    for (int kb = 0; kb < 16; kb++) {
        if (kb < 15) {
            const int st = (kb + 1) & 1;
            const int ko = (kb + 1) * 64;
#pragma unroll
            for (int p = 0; p < 4; p++) {
                int row = r0 + p * 32;
                uint32_t d = sb + st * 4 * GTILE + row * RB + u * 16;
                cpasync16(d,           Ah + (size_t)(m0 + row) * D_ + ko + u * 8);
                cpasync16(d + GTILE,   Al + (size_t)(m0 + row) * D_ + ko + u * 8);
                cpasync16(d + 2*GTILE, Bh + (size_t)(n0 + row) * D_ + ko + u * 8);
                cpasync16(d + 3*GTILE, Bl + (size_t)(n0 + row) * D_ + ko + u * 8);
            }
            CP_COMMIT();
            CP_WAIT(1);
        } else {
            CP_WAIT(0);
        }
        __syncthreads();

        const uint32_t base = sb + (kb & 1) * 4 * GTILE;
#pragma unroll
        for (int ks = 0; ks < 4; ks++) {
            uint32_t aH[2][4], aL[2][4];
#pragma unroll
            for (int mt = 0; mt < 2; mt++) {
                uint32_t ad = base + (mw + 16*mt + (t & 15)) * RB + ks * 32 + (t >> 4) * 16;
                ldsm4(aH[mt], ad);
                ldsm4(aL[mt], ad + GTILE);
            }
#pragma unroll
            for (int np = 0; np < 4; np++) {
                uint32_t bH[4], bL[4];
                uint32_t ad = base + 2*GTILE
                            + (nw + np*16 + ((t >> 4) << 3) + (t & 7)) * RB
                            + ks * 32 + ((t >> 3) & 1) * 16;
                ldsm4(bH, ad);
                ldsm4(bL, ad + GTILE);
#pragma unroll
                for (int mt = 0; mt < 2; mt++) {
                    mma_bf16(c[mt][2*np],   aH[mt], bH);
                    mma_bf16(c[mt][2*np],   aH[mt], bL);
                    mma_bf16(c[mt][2*np],   aL[mt], bH);
                    mma_bf16(c[mt][2*np+1], aH[mt], bH + 2);
                    mma_bf16(c[mt][2*np+1], aH[mt], bL + 2);
                    mma_bf16(c[mt][2*np+1], aL[mt], bH + 2);
                }
            }
        }
        __syncthreads();
    }

    // ---- epilogue
    const int g = t >> 2, i2 = (t & 3) * 2;
    if (MODE == 0) {
        const int z = n0 >> 10;
        const float scale = (z == 0) ? 0.125f : 1.0f;
        const float* bias = (z == 0) ? bq : (z == 1) ? bk : bv;
        __nv_bfloat16* dHi = (z == 0) ? g_qHi : (z == 1) ? g_kHi : g_vHi;
        __nv_bfloat16* dLo = (z == 0) ? g_qLo : (z == 1) ? g_kLo : g_vLo;
#pragma unroll
        for (int mt = 0; mt < 2; mt++) {
#pragma unroll
            for (int rr = 0; rr < 2; rr++) {
                const int m = m0 + mw + 16*mt + g + rr*8;
                const int b = m >> 11, s = m & (S_ - 1);
#pragma unroll
                for (int nt = 0; nt < 8; nt++) {
                    const int col = nw + nt*8 + i2;
                    const int nin = (n0 & 1023) + col;
                    const int h = nin >> 6, e = nin & 63;
                    float v0 = (c[mt][nt][rr*2+0] + bias[nin])   * scale;
                    float v1 = (c[mt][nt][rr*2+1] + bias[nin+1]) * scale;
                    uint32_t hi, lo;
                    pack_hl(v0, v1, hi, lo);
                    size_t off = ((size_t)(b * H_ + h) * S_ + s) * DH_ + e;
                    *(uint32_t*)(dHi + off) = hi;
                    *(uint32_t*)(dLo + off) = lo;
                }
            }
        }
    } else {
#pragma unroll
        for (int mt = 0; mt < 2; mt++) {
#pragma unroll
            for (int rr = 0; rr < 2; rr++) {
                const int m = m0 + mw + 16*mt + g + rr*8;
#pragma unroll
                for (int nt = 0; nt < 8; nt++) {
                    const int col = n0 + nw + nt*8 + i2;
                    float2 v;
                    v.x = c[mt][nt][rr*2+0] + bo[col];
                    v.y = c[mt][nt][rr*2+1] + bo[col+1];
                    *(float2*)(out + (size_t)m * D_ + col) = v;
                }
            }
        }
    }
}

// ---------------------------------------------------------------------------
// mma.sync flash attention: 128 q-rows per CTA, 8 warps x 16 rows, 64-key blocks.
// smem: Qhi/Qlo [128][72]bf16, Khi/Klo/Vhi/Vlo [64][72]bf16 = 73728 B
#define QT    (128*RB)     // 18432
#define KT    (64*RB)      // 9216
#define ATTN_SMEM (2*QT + 4*KT)

__global__ __launch_bounds__(256)
void mma_attn()
{
    extern __shared__ char smem[];
    const uint32_t sb = smem_u32(smem);
    const int tid = threadIdx.x, w = tid >> 5, t = tid & 31;
    const int qb = blockIdx.x, bh = blockIdx.y;
    const size_t hb = (size_t)bh * S_ * DH_;

    const uint32_t QH = sb, QL = sb + QT;
    const uint32_t KH = sb + 2*QT, KL = KH + KT, VH = KL + KT, VL = VH + KT;

    // load Q tiles (rows qb*128 .. +127)
    {
        const int u = tid & 7, r0 = tid >> 3;
#pragma unroll
        for (int p = 0; p < 4; p++) {
            int row = r0 + p * 32;
            size_t src = hb + (size_t)(qb * 128 + row) * DH_ + u * 8;
            cpasync16(QH + row * RB + u * 16, g_qHi + src);
            cpasync16(QL + row * RB + u * 16, g_qLo + src);
        }
        CP_COMMIT();
    }

    float o[8][4];
#pragma unroll
    for (int j = 0; j < 8; j++)
#pragma unroll
        for (int q = 0; q < 4; q++) o[j][q] = 0.f;
    float mr0 = -1e30f, mr1 = -1e30f, lr0 = 0.f, lr1 = 0.f;

    for (int kb = 0; kb < 32; kb++) {
        __syncthreads();            // previous PV done before overwriting K/V
        {
            const int u = tid & 7, r0 = tid >> 3;
#pragma unroll
            for (int p = 0; p < 2; p++) {
                int row = r0 + p * 32;
                size_t src = hb + (size_t)(kb * 64 + row) * DH_ + u * 8;
                uint32_t d = row * RB + u * 16;
                cpasync16(KH + d, g_kHi + src);
                cpasync16(KL + d, g_kLo + src);
                cpasync16(VH + d, g_vHi + src);
                cpasync16(VL + d, g_vLo + src);
            }
        }
        CP_COMMIT();
        CP_WAIT(0);
        __syncthreads();

        // ---- S = Q K^T (scale folded into Q), 3-term hi/lo
        float s[8][4];
#pragma unroll
        for (int j = 0; j < 8; j++)
#pragma unroll
            for (int q = 0; q < 4; q++) s[j][q] = 0.f;
#pragma unroll
        for (int ks = 0; ks < 4; ks++) {
            uint32_t aH[4], aL[4];
            uint32_t ad = QH + (w * 16 + (t & 15)) * RB + ks * 32 + (t >> 4) * 16;
            ldsm4(aH, ad);
            ldsm4(aL, ad + QT);
#pragma unroll
            for (int np = 0; np < 4; np++) {
                uint32_t bH[4], bL[4];
                uint32_t bd = KH + (np*16 + ((t >> 4) << 3) + (t & 7)) * RB
                            + ks * 32 + ((t >> 3) & 1) * 16;
                ldsm4(bH, bd);
                ldsm4(bL, bd + KT);
                mma_bf16(s[2*np],   aH, bH);
                mma_bf16(s[2*np],   aH, bL);
                mma_bf16(s[2*np],   aL, bH);
                mma_bf16(s[2*np+1], aH, bH + 2);
                mma_bf16(s[2*np+1], aH, bL + 2);
                mma_bf16(s[2*np+1], aL, bH + 2);
            }
        }

        // ---- online softmax (rows g and g+8, whole row within this warp)
        float rmax0 = -1e30f, rmax1 = -1e30f;
#pragma unroll
        for (int j = 0; j < 8; j++) {
            rmax0 = fmaxf(rmax0, fmaxf(s[j][0], s[j][1]));
            rmax1 = fmaxf(rmax1, fmaxf(s[j][2], s[j][3]));
        }
#pragma unroll
        for (int off = 1; off <= 2; off <<= 1) {
            rmax0 = fmaxf(rmax0, __shfl_xor_sync(0xffffffffu, rmax0, off));
            rmax1 = fmaxf(rmax1, __shfl_xor_sync(0xffffffffu, rmax1, off));
        }
        float mn0 = fmaxf(mr0, rmax0), mn1 = fmaxf(mr1, rmax1);
        float corr0 = __expf(mr0 - mn0), corr1 = __expf(mr1 - mn1);
        mr0 = mn0; mr1 = mn1;

        float sum0 = 0.f, sum1 = 0.f;
#pragma unroll
        for (int j = 0; j < 8; j++) {
            s[j][0] = __expf(s[j][0] - mn0);
            s[j][1] = __expf(s[j][1] - mn0);
            s[j][2] = __expf(s[j][2] - mn1);
            s[j][3] = __expf(s[j][3] - mn1);
            sum0 += s[j][0] + s[j][1];
            sum1 += s[j][2] + s[j][3];
        }
#pragma unroll
        for (int off = 1; off <= 2; off <<= 1) {
            sum0 += __shfl_xor_sync(0xffffffffu, sum0, off);
            sum1 += __shfl_xor_sync(0xffffffffu, sum1, off);
        }
        lr0 = lr0 * corr0 + sum0;
        lr1 = lr1 * corr1 + sum1;
#pragma unroll
        for (int j = 0; j < 8; j++) {
            o[j][0] *= corr0; o[j][1] *= corr0;
            o[j][2] *= corr1; o[j][3] *= corr1;
        }

        // ---- pack P into PV A-fragments (register-only, no smem roundtrip)
        uint32_t pH[4][4], pL[4][4];
#pragma unroll
        for (int kk = 0; kk < 4; kk++) {
            pack_hl(s[2*kk][0],   s[2*kk][1],   pH[kk][0], pL[kk][0]);
            pack_hl(s[2*kk][2],   s[2*kk][3],   pH[kk][1], pL[kk][1]);
            pack_hl(s[2*kk+1][0], s[2*kk+1][1], pH[kk][2], pL[kk][2]);
            pack_hl(s[2*kk+1][2], s[2*kk+1][3], pH[kk][3], pL[kk][3]);
        }

        // ---- O += P V, 3-term hi/lo, V via ldmatrix.trans
#pragma unroll
        for (int kk = 0; kk < 4; kk++) {
#pragma unroll
            for (int jp = 0; jp < 4; jp++) {
                uint32_t vHf[4], vLf[4];
                uint32_t vd = VH + (kk*16 + (t & 7) + (((t >> 3) & 1) << 3)) * RB
                            + jp * 32 + ((t >> 4) << 4);
                ldsm4t(vHf, vd);
                ldsm4t(vLf, vd + KT);
                mma_bf16(o[2*jp],   pH[kk], vHf);
                mma_bf16(o[2*jp],   pL[kk], vHf);
                mma_bf16(o[2*jp],   pH[kk], vLf);
                mma_bf16(o[2*jp+1], pH[kk], vHf + 2);
                mma_bf16(o[2*jp+1], pL[kk], vHf + 2);
                mma_bf16(o[2*jp+1], pH[kk], vLf + 2);
            }
        }
    }

    // ---- epilogue: ctx[b*S+s][h*64+e] as bf16 hi/lo
    const float inv0 = 1.0f / lr0, inv1 = 1.0f / lr1;
    const int b = bh >> 4, h = bh & 15;
    const int srow = qb * 128 + w * 16 + (t >> 2);
    const int i2 = (t & 3) * 2;
#pragma unroll
    for (int nt = 0; nt < 8; nt++) {
        const int col = h * DH_ + nt * 8 + i2;
        uint32_t hi, lo;
        size_t off0 = (size_t)(b * S_ + srow) * D_ + col;
        pack_hl(o[nt][0] * inv0, o[nt][1] * inv0, hi, lo);
        *(uint32_t*)(g_cHi + off0) = hi;
        *(uint32_t*)(g_cLo + off0) = lo;
        size_t off1 = (size_t)(b * S_ + srow + 8) * D_ + col;
        pack_hl(o[nt][2] * inv1, o[nt][3] * inv1, hi, lo);
        *(uint32_t*)(g_cHi + off1) = hi;
        *(uint32_t*)(g_cLo + off1) = lo;
    }
}

// ---------------------------------------------------------------------------
extern "C" void kernel_launch(void* const* d_in, const int* in_sizes, int n_in,
                              void* d_out, int out_size)
{
    const float* x  = (const float*)d_in[0];
    const float* Wq = (const float*)d_in[1];
    const float* bq = (const float*)d_in[2];
    const float* Wk = (const float*)d_in[3];
    const float* bk = (const float*)d_in[4];
    const float* Wv = (const float*)d_in[5];
    const float* bv = (const float*)d_in[6];
    const float* Wo = (const float*)d_in[7];
    const float* bo = (const float*)d_in[8];
    float* out = (float*)d_out;

    static bool attr_done = false;
    if (!attr_done) {
        cudaFuncSetAttribute(mma_gemm<0>, cudaFuncAttributeMaxDynamicSharedMemorySize, GEMM_SMEM);
        cudaFuncSetAttribute(mma_gemm<1>, cudaFuncAttributeMaxDynamicSharedMemorySize, GEMM_SMEM);
        cudaFuncSetAttribute(mma_attn,    cudaFuncAttributeMaxDynamicSharedMemorySize, ATTN_SMEM);
        attr_done = true;
    }

    // operand prep: fp32 -> bf16 hi/lo
    cvt_x_kernel<<<MTOT * D_ / 4 / 256, 256>>>(x);
    __nv_bfloat16 *wHi, *wLo, *woHi, *woLo;
    cudaGetSymbolAddress((void**)&wHi,  g_wHi);
    cudaGetSymbolAddress((void**)&wLo,  g_wLo);
    cudaGetSymbolAddress((void**)&woHi, g_woHi);
    cudaGetSymbolAddress((void**)&woLo, g_woLo);
    dim3 tT(32, 8);
    cvt_T_kernel<<<dim3(D_/32, DH_/32, H_), tT>>>(Wq, wHi,             wLo,             D_, DH_);
    cvt_T_kernel<<<dim3(D_/32, DH_/32, H_), tT>>>(Wk, wHi + 1024*D_,   wLo + 1024*D_,   D_, DH_);
    cvt_T_kernel<<<dim3(D_/32, DH_/32, H_), tT>>>(Wv, wHi + 2048*D_,   wLo + 2048*D_,   D_, DH_);
    cvt_T_kernel<<<dim3(D_/32, D_/32, 1),   tT>>>(Wo, woHi,            woLo,            D_, D_);

    // fused QKV projection (tensor cores via mma.sync) -> q/k/v hi/lo [b,h,s,e]
    mma_gemm<0><<<dim3(NQKV/128, MTOT/128), 256, GEMM_SMEM>>>(bq, bk, bv, bo, out);

    // flash attention (tensor cores) -> ctx hi/lo
    mma_attn<<<dim3(S_/128, B_*H_), 256, ATTN_SMEM>>>();

    // output projection
    mma_gemm<1><<<dim3(D_/128, MTOT/128), 256, GEMM_SMEM>>>(bq, bk, bv, bo, out);
}